// round 11
// baseline (speedup 1.0000x reference)
#include <cuda_runtime.h>
#include <cstdint>

// HeteroEmbedding: out[n] = tables[types[n], x[n]]  (row 0 of each table is zero,
// so the padding mask is implicit in the gather).
//
// Inputs (metadata order) — NOTE: JAX without x64 delivers int32 indices:
//   d_in[0]: x      int32 [N]
//   d_in[1]: types  int32 [N]
//   d_in[2]: tables float32 [8, 50000, 128]
// Output: float32 [N, 128]

#define VOCAB 50000
#define EMBED 128
#define F4_PER_ROW (EMBED / 4)   // 32 float4 per row == 1 warp, 1 float4/lane

__global__ void __launch_bounds__(256)
hetero_embed_kernel(const int* __restrict__ x,
                    const int* __restrict__ types,
                    const float4* __restrict__ tables,
                    float4* __restrict__ out,
                    int n)
{
    // one warp per row
    int warp = (int)((blockIdx.x * (unsigned)blockDim.x + threadIdx.x) >> 5);
    int lane = threadIdx.x & 31;
    if (warp >= n) return;

    // all lanes load the same 4B word -> single sector, broadcast
    int xi = __ldg(&x[warp]);
    int ti = __ldg(&types[warp]);

    size_t row_f4 = ((size_t)ti * VOCAB + (size_t)xi) * F4_PER_ROW;

    // table read: default/L2 caching — hot rows get ~5x average reuse
    float4 v = __ldg(&tables[row_f4 + lane]);

    // streaming output: evict-first so the 1GB write stream doesn't evict hot table rows
    __stcs(&out[(size_t)warp * F4_PER_ROW + lane], v);
}

extern "C" void kernel_launch(void* const* d_in, const int* in_sizes, int n_in,
                              void* d_out, int out_size)
{
    const int*    x      = (const int*)d_in[0];
    const int*    types  = (const int*)d_in[1];
    const float4* tables = (const float4*)d_in[2];
    float4*       out    = (float4*)d_out;

    int n = in_sizes[0];                 // N rows
    long long total_threads = (long long)n * 32;   // one warp per row
    int block = 256;
    int grid = (int)((total_threads + block - 1) / block);

    hetero_embed_kernel<<<grid, block>>>(x, types, tables, out, n);
}

// round 12
// speedup vs baseline: 1.3431x; 1.3431x over previous
#include <cuda_runtime.h>
#include <cstdint>

// HeteroEmbedding: out[n] = tables[types[n], x[n]]  (row 0 of each table is zero,
// so the padding mask is implicit in the gather).
//
// Inputs (metadata order):
//   d_in[0]: x      int32 [N]
//   d_in[1]: types  int32 [N]
//   d_in[2]: tables float32 [8, 50000, 128]
// Output: float32 [N, 128]
//
// Strategy: HBM-bound gather. 4 rows per warp ->
//   - 2x int4 broadcast index loads (2 sectors) amortize index latency 4x
//   - 4 independent 512B row reads in flight (MLP=4) hide DRAM latency
//   - 2KB contiguous evict-first store burst per warp

#define VOCAB 50000
#define EMBED 128
#define F4_PER_ROW (EMBED / 4)   // 32 float4 per row: 1 float4 per lane

__global__ void __launch_bounds__(256)
hetero_embed_kernel(const int* __restrict__ x,
                    const int* __restrict__ types,
                    const float4* __restrict__ tables,
                    float4* __restrict__ out,
                    int n)
{
    int warp = (int)((blockIdx.x * (unsigned)blockDim.x + threadIdx.x) >> 5);
    int lane = threadIdx.x & 31;
    int base = warp * 4;
    if (base >= n) return;

    if (base + 3 < n) {
        // all lanes load the same 16B -> single sector, broadcast
        int4 xi = __ldg((const int4*)(x + base));
        int4 ti = __ldg((const int4*)(types + base));

        size_t r0 = ((size_t)ti.x * VOCAB + (size_t)xi.x) * F4_PER_ROW + lane;
        size_t r1 = ((size_t)ti.y * VOCAB + (size_t)xi.y) * F4_PER_ROW + lane;
        size_t r2 = ((size_t)ti.z * VOCAB + (size_t)xi.z) * F4_PER_ROW + lane;
        size_t r3 = ((size_t)ti.w * VOCAB + (size_t)xi.w) * F4_PER_ROW + lane;

        // 4 independent 512B row gathers -> MLP=4 per warp
        float4 v0 = __ldg(&tables[r0]);
        float4 v1 = __ldg(&tables[r1]);
        float4 v2 = __ldg(&tables[r2]);
        float4 v3 = __ldg(&tables[r3]);

        // 2KB contiguous streaming store burst (evict-first: protect L2 table residency)
        float4* o = out + (size_t)base * F4_PER_ROW + lane;
        __stcs(o + 0 * F4_PER_ROW, v0);
        __stcs(o + 1 * F4_PER_ROW, v1);
        __stcs(o + 2 * F4_PER_ROW, v2);
        __stcs(o + 3 * F4_PER_ROW, v3);
    } else {
        // scalar tail (N % 4 != 0 safety)
        for (int r = base; r < n; r++) {
            int xi = __ldg(&x[r]);
            int ti = __ldg(&types[r]);
            size_t rf = ((size_t)ti * VOCAB + (size_t)xi) * F4_PER_ROW + lane;
            float4 v = __ldg(&tables[rf]);
            __stcs(&out[(size_t)r * F4_PER_ROW + lane], v);
        }
    }
}

extern "C" void kernel_launch(void* const* d_in, const int* in_sizes, int n_in,
                              void* d_out, int out_size)
{
    const int*    x      = (const int*)d_in[0];
    const int*    types  = (const int*)d_in[1];
    const float4* tables = (const float4*)d_in[2];
    float4*       out    = (float4*)d_out;

    int n = in_sizes[0];                               // N rows
    long long warps = ((long long)n + 3) / 4;          // 4 rows per warp
    long long total_threads = warps * 32;
    int block = 256;
    int grid = (int)((total_threads + block - 1) / block);

    hetero_embed_kernel<<<grid, block>>>(x, types, tables, out, n);
}